// round 6
// baseline (speedup 1.0000x reference)
#include <cuda_runtime.h>

#define TT 128
#define BB 64
#define HH 128
#define EE0 128
#define EE1 64
#define TB (TT*BB)
#define LOG2E 1.4426950408889634f

// Scratch (device globals: no allocation allowed in kernel_launch)
__device__ float g_ms[TT*BB*HH];    // running mean  [T,B,H]
__device__ float g_x1T[BB*HH*TT];   // x1 transposed [B,H,T]
__device__ float g_q[TT*BB*HH];     // x2 + wms      [T,B,H]
__device__ float g_ma[TT*BB*HH];    // m_a           [T,B,H]

__device__ __forceinline__ float fex2(float x){ float r; asm("ex2.approx.f32 %0, %1;" : "=f"(r) : "f"(x)); return r; }
__device__ __forceinline__ float frcp(float x){ float r; asm("rcp.approx.f32 %0, %1;" : "=f"(r) : "f"(x)); return r; }
__device__ __forceinline__ float ftanh(float x){ float r; asm("tanh.approx.f32 %0, %1;" : "=f"(r) : "f"(x)); return r; }
__device__ __forceinline__ float sigmoidf_(float x){ return frcp(1.0f + fex2(x * -LOG2E)); }
__device__ __forceinline__ float leakyf_(float x){ return x > 0.0f ? x : 0.3f * x; }

// ---------------------------------------------------------------------------
// K1: running mean over time prefix (frozen).
// ---------------------------------------------------------------------------
__global__ __launch_bounds__(128) void k_cumsum(const float* __restrict__ in) {
    int idx = blockIdx.x * 128 + threadIdx.x;   // b*H + h
    float acc = 0.0f;
#pragma unroll 4
    for (int t = 0; t < TT; t++) {
        acc += in[t * (BB*HH) + idx];
        g_ms[t * (BB*HH) + idx] = acc / (float)(t + 1);
    }
}

// ---------------------------------------------------------------------------
// K2: fused x1 = in@w1 + b1 (stored transposed [B,H,T]); q = in@w2 + ms@w3.
// (frozen R2 version)
// ---------------------------------------------------------------------------
__global__ __launch_bounds__(256) void k_gemm1(
    const float* __restrict__ in,
    const float* __restrict__ w1, const float* __restrict__ w1b,
    const float* __restrict__ w2, const float* __restrict__ w3)
{
    __shared__ float s_in[HH][36];
    __shared__ float s_ms[HH][36];
    int tid = threadIdx.x;
    int row0 = blockIdx.x * 32;

    for (int idx = tid; idx < 32 * HH; idx += 256) {
        int r = idx >> 7, h = idx & 127;
        s_in[h][r] = in[(row0 + r) * HH + h];
        s_ms[h][r] = g_ms[(row0 + r) * HH + h];
    }
    __syncthreads();

    int c = tid & 127;
    int rh = tid >> 7;           // 0/1 -> rows rh*16 .. rh*16+15
    float a1[16], a2[16];
#pragma unroll
    for (int r = 0; r < 16; r++) { a1[r] = 0.0f; a2[r] = 0.0f; }

    for (int h = 0; h < HH; h++) {
        float w1v = w1[h * HH + c];
        float w2v = w2[h * HH + c];
        float w3v = w3[h * HH + c];
        const float4* pi = (const float4*)&s_in[h][rh * 16];
        const float4* pm = (const float4*)&s_ms[h][rh * 16];
#pragma unroll
        for (int k = 0; k < 4; k++) {
            float4 vi = pi[k];
            float4 vm = pm[k];
            a1[4*k+0] = fmaf(vi.x, w1v, a1[4*k+0]);
            a1[4*k+1] = fmaf(vi.y, w1v, a1[4*k+1]);
            a1[4*k+2] = fmaf(vi.z, w1v, a1[4*k+2]);
            a1[4*k+3] = fmaf(vi.w, w1v, a1[4*k+3]);
            a2[4*k+0] = fmaf(vi.x, w2v, fmaf(vm.x, w3v, a2[4*k+0]));
            a2[4*k+1] = fmaf(vi.y, w2v, fmaf(vm.y, w3v, a2[4*k+1]));
            a2[4*k+2] = fmaf(vi.z, w2v, fmaf(vm.z, w3v, a2[4*k+2]));
            a2[4*k+3] = fmaf(vi.w, w2v, fmaf(vm.w, w3v, a2[4*k+3]));
        }
    }
    float bias = w1b[c];
#pragma unroll
    for (int r = 0; r < 16; r++) {
        int grow = row0 + rh * 16 + r;
        int t = grow >> 6;        // row = t*B + b
        int b = grow & 63;
        g_x1T[(b * HH + c) * TT + t] = a1[r] + bias;
        g_q[grow * HH + c] = a2[r];
    }
}

// ---------------------------------------------------------------------------
// K3: scores + m_a, i-tiled (frozen R2 version).
// ---------------------------------------------------------------------------
__global__ __launch_bounds__(256) void k_scores(
    const float* __restrict__ in, const float* __restrict__ w0)
{
    int i0 = blockIdx.x * 16;
    int b  = blockIdx.y;
    __shared__ float qh[16][HH];      // 0.5 * q[i,b,:]
    __shared__ float w0s[HH];
    __shared__ float ssh[16][132];    // scores, padded
    __shared__ float w0sum_sh;

    int tid = threadIdx.x;
    for (int idx = tid; idx < 16 * HH; idx += 256) {
        int il = idx >> 7, h = idx & 127;
        qh[il][h] = g_q[((i0 + il) * BB + b) * HH + h] * 0.5f;
    }
    if (tid < 128) w0s[tid] = w0[tid];
    __syncthreads();
    if (tid < 32) {
        float s = w0s[tid] + w0s[tid+32] + w0s[tid+64] + w0s[tid+96];
#pragma unroll
        for (int off = 16; off; off >>= 1) s += __shfl_xor_sync(0xFFFFFFFFu, s, off);
        if (tid == 0) w0sum_sh = s;
    }
    __syncthreads();
    float w0sum = w0sum_sh;

    // ---- phase 1: scores ----
    int j  = tid & 127;
    int ih = (tid >> 7) * 8;          // 8 i's per thread
    float acc[8];
#pragma unroll
    for (int k = 0; k < 8; k++) acc[k] = 0.0f;

    if (j < i0 + 16) {                // causally relevant j only
        const float* xp = g_x1T + b * (HH * TT) + j;
        for (int h = 0; h < HH; h++) {
            float x1v = xp[h * TT] * 0.5f;
            float wv = w0s[h];
#pragma unroll
            for (int k = 0; k < 8; k++) {
                float t = ftanh(x1v + qh[ih + k][h]);
                acc[k] = fmaf(wv, t, acc[k]);
            }
        }
    }
#pragma unroll
    for (int k = 0; k < 8; k++) {
        int ig = i0 + ih + k;
        ssh[ih + k][j] = (j <= ig) ? 0.5f * (acc[k] + w0sum) : 0.0f;
    }
    __syncthreads();

    // ---- phase 2: m_a ----
    int h   = tid & 127;
    int ih2 = (tid >> 7) * 8;
    float m[8];
#pragma unroll
    for (int k = 0; k < 8; k++) m[k] = 0.0f;

    const float* ip = in + b * HH + h;
    int jmax = i0 + 16;
    for (int jj = 0; jj < jmax; jj += 4) {
        float v0 = ip[(jj + 0) * (BB*HH)];
        float v1 = ip[(jj + 1) * (BB*HH)];
        float v2 = ip[(jj + 2) * (BB*HH)];
        float v3 = ip[(jj + 3) * (BB*HH)];
#pragma unroll
        for (int k = 0; k < 8; k++) {
            float4 s4 = *(const float4*)&ssh[ih2 + k][jj];
            m[k] = fmaf(s4.x, v0, fmaf(s4.y, v1, fmaf(s4.z, v2, fmaf(s4.w, v3, m[k]))));
        }
    }
#pragma unroll
    for (int k = 0; k < 8; k++)
        g_ma[((i0 + ih2 + k) * BB + b) * HH + h] = m[k];
}

// ---------------------------------------------------------------------------
// K4: predict heads, v3. 16 rows/block, grid (512, 2): blockIdx.y = pass.
// Weight tiles staged through SHARED MEMORY (16 h at a time, cooperative
// coalesced load) -> inner loop is pure LDS+FMA, no LDG latency to hide.
// Layer0: 4 cols x 4 rows/thread. Layer1: 4 cols x 2 rows/thread.
// ---------------------------------------------------------------------------
__global__ __launch_bounds__(256) void k_predict(
    const float* __restrict__ in,
    const float* __restrict__ c0a, const float* __restrict__ c0ab,
    const float* __restrict__ c0b, const float* __restrict__ c0bb,
    const float* __restrict__ c1a, const float* __restrict__ c1ab,
    const float* __restrict__ c1b, const float* __restrict__ c1bb,
    const float* __restrict__ v0a, const float* __restrict__ v0ab,
    const float* __restrict__ v0b, const float* __restrict__ v0bb,
    const float* __restrict__ v1a, const float* __restrict__ v1ab,
    const float* __restrict__ v1b, const float* __restrict__ v1bb,
    float* __restrict__ out)
{
    __shared__ float s_in[2][HH][20];   // [branch][h][row0..15 + pad]
    __shared__ float s_w[2][16][128];   // weight tile; reused as sl1 at end

    const int ROWS = 16;
    int tid    = threadIdx.x;
    int row0   = blockIdx.x * ROWS;
    int pass   = blockIdx.y;
    int branch = tid >> 7;              // 0: a-side (m_a), 1: b-side (inputs)
    int t7     = tid & 127;

    const float *k0, *k0bias, *k1, *k1bias;
    if (pass == 0) { k0 = branch ? c0b : c0a; k0bias = branch ? c0bb : c0ab;
                     k1 = branch ? c1b : c1a; k1bias = branch ? c1bb : c1ab; }
    else           { k0 = branch ? v0b : v0a; k0bias = branch ? v0bb : v0ab;
                     k1 = branch ? v1b : v1a; k1bias = branch ? v1bb : v1ab; }

    // ---- load inputs transposed [h][row] ----
    for (int idx = tid; idx < ROWS * HH; idx += 256) {
        int h = idx & 127, r = idx >> 7;
        s_in[0][h][r] = g_ma[(row0 + r) * HH + h];
        s_in[1][h][r] = in[(row0 + r) * HH + h];
    }

    // ---- layer 0: [16,128] x [128,128] per branch, 4 cols x 4 rows/thread --
    int cg = t7 & 31;               // cols cg*4 .. cg*4+3  (== lane)
    int rg = t7 >> 5;               // rows rg*4 .. rg*4+3  (== warp-in-branch)
    float a0[16];
#pragma unroll
    for (int x = 0; x < 16; x++) a0[x] = 0.0f;

    const float4* k0v = (const float4*)k0;
    float4* swv = (float4*)&s_w[branch][0][0];
    for (int t = 0; t < 8; t++) {
        int h0 = t * 16;
        // cooperative weight tile load: 512 float4 per branch, 4 per thread
#pragma unroll
        for (int kk = 0; kk < 4; kk++) {
            int lin = kk * 128 + t7;              // 0..511
            swv[lin] = k0v[(h0 + (lin >> 5)) * 32 + (lin & 31)];
        }
        __syncthreads();
#pragma unroll
        for (int hl = 0; hl < 16; hl++) {
            float4 w4 = swv[hl * 32 + cg];                       // conflict-free
            float4 v4 = *(const float4*)&s_in[branch][h0 + hl][rg * 4]; // bcast
            float wv[4] = {w4.x, w4.y, w4.z, w4.w};
            float rv[4] = {v4.x, v4.y, v4.z, v4.w};
#pragma unroll
            for (int cc = 0; cc < 4; cc++)
#pragma unroll
                for (int rr = 0; rr < 4; rr++)
                    a0[cc * 4 + rr] = fmaf(wv[cc], rv[rr], a0[cc * 4 + rr]);
        }
        __syncthreads();
    }
    float4 b0v = *(const float4*)&k0bias[cg * 4];
    float b0[4] = {b0v.x, b0v.y, b0v.z, b0v.w};
    // write activated layer0 outputs back into s_in (all reads done: last sync)
#pragma unroll
    for (int cc = 0; cc < 4; cc++) {
        float4 t0 = make_float4(leakyf_(a0[cc * 4 + 0] + b0[cc]),
                                leakyf_(a0[cc * 4 + 1] + b0[cc]),
                                leakyf_(a0[cc * 4 + 2] + b0[cc]),
                                leakyf_(a0[cc * 4 + 3] + b0[cc]));
        *(float4*)&s_in[branch][cg * 4 + cc][rg * 4] = t0;
    }
    __syncthreads();

    // ---- layer 1: [16,128] x [128,64] per branch, 4 cols x 2 rows/thread --
    int cg2 = t7 & 15;              // cols cg2*4 of 64
    int rg2 = t7 >> 4;              // rows rg2*2 of 16
    float a1[8];
#pragma unroll
    for (int x = 0; x < 8; x++) a1[x] = 0.0f;

    const float4* k1v = (const float4*)k1;
    for (int t = 0; t < 8; t++) {
        int h0 = t * 16;
        // tile: 16 rows x 16 float4 = 256 float4 per branch, 2 per thread
#pragma unroll
        for (int kk = 0; kk < 2; kk++) {
            int lin = kk * 128 + t7;              // 0..255
            swv[lin] = k1v[(h0 + (lin >> 4)) * 16 + (lin & 15)];
        }
        __syncthreads();
#pragma unroll
        for (int hl = 0; hl < 16; hl++) {
            float4 w4 = swv[hl * 16 + cg2];
            float2 v2 = *(const float2*)&s_in[branch][h0 + hl][rg2 * 2];
            float wv[4] = {w4.x, w4.y, w4.z, w4.w};
#pragma unroll
            for (int cc = 0; cc < 4; cc++) {
                a1[cc * 2 + 0] = fmaf(wv[cc], v2.x, a1[cc * 2 + 0]);
                a1[cc * 2 + 1] = fmaf(wv[cc], v2.y, a1[cc * 2 + 1]);
            }
        }
        __syncthreads();
    }
    float4 b1v = *(const float4*)&k1bias[cg2 * 4];
    float b1[4] = {b1v.x, b1v.y, b1v.z, b1v.w};

    // write activated layer1 outputs into s_w region (weights dead after sync)
    float* sl1 = &s_w[0][0][0];     // [branch*16+row][68]
#pragma unroll
    for (int rr = 0; rr < 2; rr++) {
        int row = rg2 * 2 + rr;
        float4 v = make_float4(leakyf_(a1[0 * 2 + rr] + b1[0]),
                               leakyf_(a1[1 * 2 + rr] + b1[1]),
                               leakyf_(a1[2 * 2 + rr] + b1[2]),
                               leakyf_(a1[3 * 2 + rr] + b1[3]));
        *(float4*)&sl1[(branch * 16 + row) * 68 + cg2 * 4] = v;
    }
    __syncthreads();

    // ---- product + reduce + sigmoid ----
    int row = tid >> 4;             // 0..15
    int lg  = tid & 15;             // 16 lanes per row, 4 elems each
    float4 a4 = *(const float4*)&sl1[(0 * 16 + row) * 68 + lg * 4];
    float4 b4 = *(const float4*)&sl1[(1 * 16 + row) * 68 + lg * 4];
    float p = a4.x*b4.x + a4.y*b4.y + a4.z*b4.z + a4.w*b4.w;
    p += __shfl_xor_sync(0xFFFFFFFFu, p, 8);
    p += __shfl_xor_sync(0xFFFFFFFFu, p, 4);
    p += __shfl_xor_sync(0xFFFFFFFFu, p, 2);
    p += __shfl_xor_sync(0xFFFFFFFFu, p, 1);
    if (lg == 0)
        out[pass * TB + row0 + row] = sigmoidf_(p);
}

// ---------------------------------------------------------------------------
// K5: out[TB+i] *= out[i]  (pv = raw_pv * pc)
// ---------------------------------------------------------------------------
__global__ __launch_bounds__(256) void k_mul(float* __restrict__ out) {
    int i = blockIdx.x * 256 + threadIdx.x;
    out[TB + i] *= out[i];
}

// ---------------------------------------------------------------------------
extern "C" void kernel_launch(void* const* d_in, const int* in_sizes, int n_in,
                              void* d_out, int out_size)
{
    (void)in_sizes; (void)n_in; (void)out_size;
    const float* in_  = (const float*)d_in[0];
    const float* w1k  = (const float*)d_in[1];
    const float* w1b  = (const float*)d_in[2];
    const float* w2k  = (const float*)d_in[3];
    const float* w3k  = (const float*)d_in[4];
    const float* w0k  = (const float*)d_in[5];
    const float* pc0a = (const float*)d_in[6];
    const float* pc0ab= (const float*)d_in[7];
    const float* pc0b = (const float*)d_in[8];
    const float* pc0bb= (const float*)d_in[9];
    const float* pc1a = (const float*)d_in[10];
    const float* pc1ab= (const float*)d_in[11];
    const float* pc1b = (const float*)d_in[12];
    const float* pc1bb= (const float*)d_in[13];
    const float* pv0a = (const float*)d_in[14];
    const float* pv0ab= (const float*)d_in[15];
    const float* pv0b = (const float*)d_in[16];
    const float* pv0bb= (const float*)d_in[17];
    const float* pv1a = (const float*)d_in[18];
    const float* pv1ab= (const float*)d_in[19];
    const float* pv1b = (const float*)d_in[20];
    const float* pv1bb= (const float*)d_in[21];
    float* out = (float*)d_out;

    k_cumsum<<<BB*HH/128, 128>>>(in_);
    k_gemm1<<<TB/32, 256>>>(in_, w1k, w1b, w2k, w3k);
    k_scores<<<dim3(TT/16, BB), 256>>>(in_, w0k);
    k_predict<<<dim3(TB/16, 2), 256>>>(in_,
        pc0a, pc0ab, pc0b, pc0bb, pc1a, pc1ab, pc1b, pc1bb,
        pv0a, pv0ab, pv0b, pv0bb, pv1a, pv1ab, pv1b, pv1bb,
        out);
    k_mul<<<TB/256, 256>>>(out);
}

// round 8
// speedup vs baseline: 1.0220x; 1.0220x over previous
#include <cuda_runtime.h>

#define TT 128
#define BB 64
#define HH 128
#define EE0 128
#define EE1 64
#define TB (TT*BB)
#define LOG2E 1.4426950408889634f

// Scratch (device globals: no allocation allowed in kernel_launch)
__device__ float g_ms[TT*BB*HH];    // running mean  [T,B,H]
__device__ float g_x1T[BB*HH*TT];   // x1 transposed [B,H,T]
__device__ float g_q[TT*BB*HH];     // x2 + wms      [T,B,H]
__device__ float g_ma[TT*BB*HH];    // m_a           [T,B,H]
__device__ float g_l1[4*EE1*TB];    // layer1 outs [pass*2+branch][c][row]

__device__ __forceinline__ float fex2(float x){ float r; asm("ex2.approx.f32 %0, %1;" : "=f"(r) : "f"(x)); return r; }
__device__ __forceinline__ float frcp(float x){ float r; asm("rcp.approx.f32 %0, %1;" : "=f"(r) : "f"(x)); return r; }
__device__ __forceinline__ float ftanh(float x){ float r; asm("tanh.approx.f32 %0, %1;" : "=f"(r) : "f"(x)); return r; }
__device__ __forceinline__ float sigmoidf_(float x){ return frcp(1.0f + fex2(x * -LOG2E)); }
__device__ __forceinline__ float leakyf_(float x){ return x > 0.0f ? x : 0.3f * x; }

// ---------------------------------------------------------------------------
// K1: running mean over time prefix (frozen).
// ---------------------------------------------------------------------------
__global__ __launch_bounds__(128) void k_cumsum(const float* __restrict__ in) {
    int idx = blockIdx.x * 128 + threadIdx.x;   // b*H + h
    float acc = 0.0f;
#pragma unroll 4
    for (int t = 0; t < TT; t++) {
        acc += in[t * (BB*HH) + idx];
        g_ms[t * (BB*HH) + idx] = acc / (float)(t + 1);
    }
}

// ---------------------------------------------------------------------------
// K2: fused x1 = in@w1 + b1 (transposed out); q = in@w2 + ms@w3.
// 16 rows/block (grid 512), weights staged via DOUBLE-BUFFERED smem tiles
// (3 streams x 8 h = 12KB/buf) -> inner loop pure LDS+FMA, 1 sync/tile.
// ---------------------------------------------------------------------------
__global__ __launch_bounds__(256) void k_gemm1(
    const float* __restrict__ in,
    const float* __restrict__ w1, const float* __restrict__ w1b,
    const float* __restrict__ w2, const float* __restrict__ w3)
{
    __shared__ float s_in[HH][20];
    __shared__ float s_ms[HH][20];
    __shared__ float s_w[2][3][8][128];    // 24 KB double-buffered tile
    int tid = threadIdx.x;
    int row0 = blockIdx.x * 16;

    for (int idx = tid; idx < 16 * HH; idx += 256) {
        int r = idx >> 7, h = idx & 127;
        s_in[h][r] = in[(row0 + r) * HH + h];
        s_ms[h][r] = g_ms[(row0 + r) * HH + h];
    }

    const float4* w1v4 = (const float4*)w1;
    const float4* w2v4 = (const float4*)w2;
    const float4* w3v4 = (const float4*)w3;
    float4* swv = (float4*)&s_w[0][0][0][0];   // [2][3][8][32] float4 view

    // preload tile 0
    {
        int hh = tid >> 5, c4 = tid & 31;
        swv[tid]       = w1v4[hh * 32 + c4];       // stream 0
        swv[256 + tid] = w2v4[hh * 32 + c4];       // stream 1
        swv[512 + tid] = w3v4[hh * 32 + c4];       // stream 2
    }
    __syncthreads();

    int c = tid & 127;
    int rh = tid >> 7;           // 0/1 -> rows rh*8 .. rh*8+7
    float a1[8], a2[8];
#pragma unroll
    for (int r = 0; r < 8; r++) { a1[r] = 0.0f; a2[r] = 0.0f; }

    for (int t = 0; t < 16; t++) {
        int cb = t & 1, nb = cb ^ 1;
        if (t + 1 < 16) {
            int h0n = (t + 1) * 8;
            int hh = tid >> 5, c4 = tid & 31;
            swv[nb*768 + 0   + tid] = w1v4[(h0n + hh) * 32 + c4];
            swv[nb*768 + 256 + tid] = w2v4[(h0n + hh) * 32 + c4];
            swv[nb*768 + 512 + tid] = w3v4[(h0n + hh) * 32 + c4];
        }
        int h0 = t * 8;
#pragma unroll
        for (int hl = 0; hl < 8; hl++) {
            float w1s = s_w[cb][0][hl][c];
            float w2s = s_w[cb][1][hl][c];
            float w3s = s_w[cb][2][hl][c];
            float4 vi0 = *(const float4*)&s_in[h0 + hl][rh * 8];
            float4 vi1 = *(const float4*)&s_in[h0 + hl][rh * 8 + 4];
            float4 vm0 = *(const float4*)&s_ms[h0 + hl][rh * 8];
            float4 vm1 = *(const float4*)&s_ms[h0 + hl][rh * 8 + 4];
            a1[0] = fmaf(vi0.x, w1s, a1[0]);
            a1[1] = fmaf(vi0.y, w1s, a1[1]);
            a1[2] = fmaf(vi0.z, w1s, a1[2]);
            a1[3] = fmaf(vi0.w, w1s, a1[3]);
            a1[4] = fmaf(vi1.x, w1s, a1[4]);
            a1[5] = fmaf(vi1.y, w1s, a1[5]);
            a1[6] = fmaf(vi1.z, w1s, a1[6]);
            a1[7] = fmaf(vi1.w, w1s, a1[7]);
            a2[0] = fmaf(vi0.x, w2s, fmaf(vm0.x, w3s, a2[0]));
            a2[1] = fmaf(vi0.y, w2s, fmaf(vm0.y, w3s, a2[1]));
            a2[2] = fmaf(vi0.z, w2s, fmaf(vm0.z, w3s, a2[2]));
            a2[3] = fmaf(vi0.w, w2s, fmaf(vm0.w, w3s, a2[3]));
            a2[4] = fmaf(vi1.x, w2s, fmaf(vm1.x, w3s, a2[4]));
            a2[5] = fmaf(vi1.y, w2s, fmaf(vm1.y, w3s, a2[5]));
            a2[6] = fmaf(vi1.z, w2s, fmaf(vm1.z, w3s, a2[6]));
            a2[7] = fmaf(vi1.w, w2s, fmaf(vm1.w, w3s, a2[7]));
        }
        __syncthreads();
    }
    float bias = w1b[c];
#pragma unroll
    for (int r = 0; r < 8; r++) {
        int grow = row0 + rh * 8 + r;
        int t = grow >> 6;        // row = t*B + b
        int b = grow & 63;
        g_x1T[(b * HH + c) * TT + t] = a1[r] + bias;
        g_q[grow * HH + c] = a2[r];
    }
}

// ---------------------------------------------------------------------------
// K3: scores + m_a, i-tiled (frozen R2 version).
// ---------------------------------------------------------------------------
__global__ __launch_bounds__(256) void k_scores(
    const float* __restrict__ in, const float* __restrict__ w0)
{
    int i0 = blockIdx.x * 16;
    int b  = blockIdx.y;
    __shared__ float qh[16][HH];      // 0.5 * q[i,b,:]
    __shared__ float w0s[HH];
    __shared__ float ssh[16][132];    // scores, padded
    __shared__ float w0sum_sh;

    int tid = threadIdx.x;
    for (int idx = tid; idx < 16 * HH; idx += 256) {
        int il = idx >> 7, h = idx & 127;
        qh[il][h] = g_q[((i0 + il) * BB + b) * HH + h] * 0.5f;
    }
    if (tid < 128) w0s[tid] = w0[tid];
    __syncthreads();
    if (tid < 32) {
        float s = w0s[tid] + w0s[tid+32] + w0s[tid+64] + w0s[tid+96];
#pragma unroll
        for (int off = 16; off; off >>= 1) s += __shfl_xor_sync(0xFFFFFFFFu, s, off);
        if (tid == 0) w0sum_sh = s;
    }
    __syncthreads();
    float w0sum = w0sum_sh;

    // ---- phase 1: scores ----
    int j  = tid & 127;
    int ih = (tid >> 7) * 8;          // 8 i's per thread
    float acc[8];
#pragma unroll
    for (int k = 0; k < 8; k++) acc[k] = 0.0f;

    if (j < i0 + 16) {                // causally relevant j only
        const float* xp = g_x1T + b * (HH * TT) + j;
        for (int h = 0; h < HH; h++) {
            float x1v = xp[h * TT] * 0.5f;
            float wv = w0s[h];
#pragma unroll
            for (int k = 0; k < 8; k++) {
                float t = ftanh(x1v + qh[ih + k][h]);
                acc[k] = fmaf(wv, t, acc[k]);
            }
        }
    }
#pragma unroll
    for (int k = 0; k < 8; k++) {
        int ig = i0 + ih + k;
        ssh[ih + k][j] = (j <= ig) ? 0.5f * (acc[k] + w0sum) : 0.0f;
    }
    __syncthreads();

    // ---- phase 2: m_a ----
    int h   = tid & 127;
    int ih2 = (tid >> 7) * 8;
    float m[8];
#pragma unroll
    for (int k = 0; k < 8; k++) m[k] = 0.0f;

    const float* ip = in + b * HH + h;
    int jmax = i0 + 16;
    for (int jj = 0; jj < jmax; jj += 4) {
        float v0 = ip[(jj + 0) * (BB*HH)];
        float v1 = ip[(jj + 1) * (BB*HH)];
        float v2 = ip[(jj + 2) * (BB*HH)];
        float v3 = ip[(jj + 3) * (BB*HH)];
#pragma unroll
        for (int k = 0; k < 8; k++) {
            float4 s4 = *(const float4*)&ssh[ih2 + k][jj];
            m[k] = fmaf(s4.x, v0, fmaf(s4.y, v1, fmaf(s4.z, v2, fmaf(s4.w, v3, m[k]))));
        }
    }
#pragma unroll
    for (int k = 0; k < 8; k++)
        g_ma[((i0 + ih2 + k) * BB + b) * HH + h] = m[k];
}

// ---------------------------------------------------------------------------
// K4: predict MLP. ONE (pass, branch) per block: grid (256, 4), 128 thr.
// 32 rows/block; layer0 tile 4 cols x 8 rows/thread (32 FMA / 2 LDS);
// weights double-buffered through smem, 1 sync per 8-h tile.
// Layer1 outputs go to g_l1; k_combine does the dot+sigmoid.
// ---------------------------------------------------------------------------
__global__ __launch_bounds__(128) void k_predict_mm(
    const float* __restrict__ in,
    const float* __restrict__ c0a, const float* __restrict__ c0ab,
    const float* __restrict__ c0b, const float* __restrict__ c0bb,
    const float* __restrict__ c1a, const float* __restrict__ c1ab,
    const float* __restrict__ c1b, const float* __restrict__ c1bb,
    const float* __restrict__ v0a, const float* __restrict__ v0ab,
    const float* __restrict__ v0b, const float* __restrict__ v0bb,
    const float* __restrict__ v1a, const float* __restrict__ v1ab,
    const float* __restrict__ v1b, const float* __restrict__ v1bb)
{
    __shared__ float s_in[HH][36];      // 18.4KB: inputs, then layer0 acts
    __shared__ float s_w[2][8][128];    // 8KB double-buffered weight tile

    int tid    = threadIdx.x;
    int row0   = blockIdx.x * 32;
    int pass   = blockIdx.y >> 1;
    int branch = blockIdx.y & 1;        // 0: a-side (m_a), 1: b-side (inputs)

    const float *k0, *k0bias, *k1, *k1bias;
    if (pass == 0) { k0 = branch ? c0b : c0a; k0bias = branch ? c0bb : c0ab;
                     k1 = branch ? c1b : c1a; k1bias = branch ? c1bb : c1ab; }
    else           { k0 = branch ? v0b : v0a; k0bias = branch ? v0bb : v0ab;
                     k1 = branch ? v1b : v1a; k1bias = branch ? v1bb : v1ab; }
    const float* src = branch ? in : g_ma;

    // ---- load inputs transposed [h][row] ----
    for (int idx = tid; idx < 32 * HH; idx += 128) {
        int h = idx & 127, r = idx >> 7;
        s_in[h][r] = src[(row0 + r) * HH + h];
    }

    // ---- layer 0: [32,128] x [128,128], 4 cols x 8 rows per thread ----
    int cg = tid & 31;               // cols cg*4 .. cg*4+3  (== lane)
    int rg = tid >> 5;               // rows rg*8 .. rg*8+7  (== warp)
    float a0[32];
#pragma unroll
    for (int x = 0; x < 32; x++) a0[x] = 0.0f;

    const float4* k0v = (const float4*)k0;
    float4* swv = (float4*)&s_w[0][0][0];  // [2][8][32] float4 view
    // preload tile 0: 8h x 32 float4 = 256; 2 per thread
    swv[tid]       = k0v[(tid >> 5) * 32 + (tid & 31)];
    swv[128 + tid] = k0v[((128 + tid) >> 5) * 32 + (tid & 31)];
    __syncthreads();

    for (int t = 0; t < 16; t++) {
        int cb = t & 1, nb = cb ^ 1;
        if (t + 1 < 16) {
            int h0n = (t + 1) * 8;
#pragma unroll
            for (int kk = 0; kk < 2; kk++) {
                int lin = kk * 128 + tid;
                swv[nb * 256 + lin] = k0v[(h0n + (lin >> 5)) * 32 + (lin & 31)];
            }
        }
        int h0 = t * 8;
#pragma unroll
        for (int hl = 0; hl < 8; hl++) {
            float4 w4 = swv[cb * 256 + hl * 32 + cg];
            float4 va = *(const float4*)&s_in[h0 + hl][rg * 8];
            float4 vb = *(const float4*)&s_in[h0 + hl][rg * 8 + 4];
            float wv[4] = {w4.x, w4.y, w4.z, w4.w};
            float rv[8] = {va.x, va.y, va.z, va.w, vb.x, vb.y, vb.z, vb.w};
#pragma unroll
            for (int cc = 0; cc < 4; cc++)
#pragma unroll
                for (int rr = 0; rr < 8; rr++)
                    a0[cc * 8 + rr] = fmaf(wv[cc], rv[rr], a0[cc * 8 + rr]);
        }
        __syncthreads();
    }
    float4 b0v = *(const float4*)&k0bias[cg * 4];
    float b0[4] = {b0v.x, b0v.y, b0v.z, b0v.w};
    // write activated layer0 outputs transposed into s_in[col][row]
#pragma unroll
    for (int cc = 0; cc < 4; cc++) {
        int col = cg * 4 + cc;
        float t0[8];
#pragma unroll
        for (int rr = 0; rr < 8; rr++) t0[rr] = leakyf_(a0[cc * 8 + rr] + b0[cc]);
        *(float4*)&s_in[col][rg * 8]     = make_float4(t0[0], t0[1], t0[2], t0[3]);
        *(float4*)&s_in[col][rg * 8 + 4] = make_float4(t0[4], t0[5], t0[6], t0[7]);
    }
    __syncthreads();

    // ---- layer 1: [32,128] x [128,64], 4 cols x 4 rows per thread ----
    int cg2 = tid & 15;              // cols cg2*4 of 64
    int rg2 = tid >> 4;              // rows rg2*4 of 32
    float a1[16];
#pragma unroll
    for (int x = 0; x < 16; x++) a1[x] = 0.0f;

    const float4* k1v = (const float4*)k1;
    // preload tile 0: 8h x 16 float4 = 128; 1 per thread
    swv[(tid >> 4) * 16 + (tid & 15)] = k1v[(tid >> 4) * 16 + (tid & 15)];
    __syncthreads();

    for (int t = 0; t < 16; t++) {
        int cb = t & 1, nb = cb ^ 1;
        if (t + 1 < 16) {
            int h0n = (t + 1) * 8;
            int hh = tid >> 4, c4 = tid & 15;
            swv[nb * 128 + hh * 16 + c4] = k1v[(h0n + hh) * 16 + c4];
        }
        int h0 = t * 8;
#pragma unroll
        for (int hl = 0; hl < 8; hl++) {
            float4 w4 = swv[cb * 128 + hl * 16 + cg2];
            float4 v4 = *(const float4*)&s_in[h0 + hl][rg2 * 4];
            float wv[4] = {w4.x, w4.y, w4.z, w4.w};
            float rv[4] = {v4.x, v4.y, v4.z, v4.w};
#pragma unroll
            for (int cc = 0; cc < 4; cc++)
#pragma unroll
                for (int rr = 0; rr < 4; rr++)
                    a1[cc * 4 + rr] = fmaf(wv[cc], rv[rr], a1[cc * 4 + rr]);
        }
        __syncthreads();
    }
    float4 b1v = *(const float4*)&k1bias[cg2 * 4];
    float b1[4] = {b1v.x, b1v.y, b1v.z, b1v.w};

    // store activated layer1 outputs: g_l1[pb][c][row], float4 over rows
    int pb = pass * 2 + branch;
#pragma unroll
    for (int cc = 0; cc < 4; cc++) {
        int cidx = cg2 * 4 + cc;
        float4 v = make_float4(leakyf_(a1[cc * 4 + 0] + b1[cc]),
                               leakyf_(a1[cc * 4 + 1] + b1[cc]),
                               leakyf_(a1[cc * 4 + 2] + b1[cc]),
                               leakyf_(a1[cc * 4 + 3] + b1[cc]));
        *(float4*)&g_l1[(pb * EE1 + cidx) * TB + row0 + rg2 * 4] = v;
    }
}

// ---------------------------------------------------------------------------
// K5: combine — dot over E1, sigmoid, pv = sig*pc. One thread per row.
// ---------------------------------------------------------------------------
__global__ __launch_bounds__(256) void k_combine(float* __restrict__ out) {
    int row = blockIdx.x * 256 + threadIdx.x;    // 0..8191
    float s0 = 0.0f, s1 = 0.0f;
#pragma unroll 8
    for (int c = 0; c < EE1; c++) {
        float a0 = g_l1[(0 * EE1 + c) * TB + row];
        float b0 = g_l1[(1 * EE1 + c) * TB + row];
        float a1 = g_l1[(2 * EE1 + c) * TB + row];
        float b1 = g_l1[(3 * EE1 + c) * TB + row];
        s0 = fmaf(a0, b0, s0);
        s1 = fmaf(a1, b1, s1);
    }
    float pc = sigmoidf_(s0);
    out[row] = pc;
    out[TB + row] = sigmoidf_(s1) * pc;
}

// ---------------------------------------------------------------------------
extern "C" void kernel_launch(void* const* d_in, const int* in_sizes, int n_in,
                              void* d_out, int out_size)
{
    (void)in_sizes; (void)n_in; (void)out_size;
    const float* in_  = (const float*)d_in[0];
    const float* w1k  = (const float*)d_in[1];
    const float* w1b  = (const float*)d_in[2];
    const float* w2k  = (const float*)d_in[3];
    const float* w3k  = (const float*)d_in[4];
    const float* w0k  = (const float*)d_in[5];
    const float* pc0a = (const float*)d_in[6];
    const float* pc0ab= (const float*)d_in[7];
    const float* pc0b = (const float*)d_in[8];
    const float* pc0bb= (const float*)d_in[9];
    const float* pc1a = (const float*)d_in[10];
    const float* pc1ab= (const float*)d_in[11];
    const float* pc1b = (const float*)d_in[12];
    const float* pc1bb= (const float*)d_in[13];
    const float* pv0a = (const float*)d_in[14];
    const float* pv0ab= (const float*)d_in[15];
    const float* pv0b = (const float*)d_in[16];
    const float* pv0bb= (const float*)d_in[17];
    const float* pv1a = (const float*)d_in[18];
    const float* pv1ab= (const float*)d_in[19];
    const float* pv1b = (const float*)d_in[20];
    const float* pv1bb= (const float*)d_in[21];
    float* out = (float*)d_out;

    k_cumsum<<<BB*HH/128, 128>>>(in_);
    k_gemm1<<<TB/16, 256>>>(in_, w1k, w1b, w2k, w3k);
    k_scores<<<dim3(TT/16, BB), 256>>>(in_, w0k);
    k_predict_mm<<<dim3(TB/32, 4), 128>>>(in_,
        pc0a, pc0ab, pc0b, pc0bb, pc1a, pc1ab, pc1b, pc1bb,
        pv0a, pv0ab, pv0b, pv0bb, pv1a, pv1ab, pv1b, pv1bb);
    k_combine<<<TB/256, 256>>>(out);
}

// round 10
// speedup vs baseline: 1.0234x; 1.0014x over previous
#include <cuda_runtime.h>

#define TT 128
#define BB 64
#define HH 128
#define EE0 128
#define EE1 64
#define TB (TT*BB)
#define LOG2E 1.4426950408889634f

// Scratch (device globals: no allocation allowed in kernel_launch)
__device__ float g_ms[TT*BB*HH];    // running mean  [T,B,H]
__device__ float g_x1T[BB*HH*TT];   // x1 transposed [B,H,T]
__device__ float g_q[TT*BB*HH];     // x2 + wms      [T,B,H]
__device__ float g_ma[TT*BB*HH];    // m_a           [T,B,H]
__device__ float g_l1[4*EE1*TB];    // layer1 outs [pass*2+branch][c][row]

__device__ __forceinline__ float fex2(float x){ float r; asm("ex2.approx.f32 %0, %1;" : "=f"(r) : "f"(x)); return r; }
__device__ __forceinline__ float frcp(float x){ float r; asm("rcp.approx.f32 %0, %1;" : "=f"(r) : "f"(x)); return r; }
__device__ __forceinline__ float ftanh(float x){ float r; asm("tanh.approx.f32 %0, %1;" : "=f"(r) : "f"(x)); return r; }
__device__ __forceinline__ float sigmoidf_(float x){ return frcp(1.0f + fex2(x * -LOG2E)); }
__device__ __forceinline__ float leakyf_(float x){ return x > 0.0f ? x : 0.3f * x; }

// ---------------------------------------------------------------------------
// K1: running mean over time prefix (frozen).
// ---------------------------------------------------------------------------
__global__ __launch_bounds__(128) void k_cumsum(const float* __restrict__ in) {
    int idx = blockIdx.x * 128 + threadIdx.x;   // b*H + h
    float acc = 0.0f;
#pragma unroll 4
    for (int t = 0; t < TT; t++) {
        acc += in[t * (BB*HH) + idx];
        g_ms[t * (BB*HH) + idx] = acc / (float)(t + 1);
    }
}

// ---------------------------------------------------------------------------
// K2 v3: predict_mm-shaped. grid (256, 2), 128 threads, 32 rows/block.
//   y==0: x1 = in@w1 + b1      (K=128)        -> g_x1T transposed
//   y==1: q  = [in|ms]@[w2;w3] (K=256 concat) -> g_q
// 4 cols x 8 rows/thread (32 FMA / 2 broadcast LDS); weights double-buffered
// through smem, 1 sync per 8-k tile.
// ---------------------------------------------------------------------------
__global__ __launch_bounds__(128) void k_gemm1(
    const float* __restrict__ in,
    const float* __restrict__ w1, const float* __restrict__ w1b,
    const float* __restrict__ w2, const float* __restrict__ w3)
{
    __shared__ float s_cat[2*HH][36];   // 36.9KB: [in rows 0..127 | ms 128..255]
    __shared__ float s_w[2][8][128];    // 8KB double-buffered weight tile

    int tid  = threadIdx.x;
    int row0 = blockIdx.x * 32;
    int y    = blockIdx.y;              // 0: x1, 1: q
    int K    = y ? 2*HH : HH;
    int NT   = K / 8;

    // ---- load input tiles transposed [k][row] ----
    if (y == 0) {
        for (int idx = tid; idx < 32 * HH; idx += 128) {
            int h = idx & 127, r = idx >> 7;
            s_cat[h][r] = in[(row0 + r) * HH + h];
        }
    } else {
        for (int idx = tid; idx < 32 * 2*HH; idx += 128) {
            int hk = idx & 255, r = idx >> 8;
            const float* p = (hk < HH) ? in : g_ms;
            s_cat[hk][r] = p[(row0 + r) * HH + (hk & 127)];
        }
    }

    int cg = tid & 31;               // cols cg*4 .. cg*4+3  (== lane)
    int rg = tid >> 5;               // rows rg*8 .. rg*8+7  (== warp)
    float a0[32];
#pragma unroll
    for (int x = 0; x < 32; x++) a0[x] = 0.0f;

    const float4* w1v4 = (const float4*)w1;
    const float4* w2v4 = (const float4*)w2;
    const float4* w3v4 = (const float4*)w3;
    float4* swv = (float4*)&s_w[0][0][0];  // [2][8][32] float4 view

    // preload tile 0: 8k x 32 float4 = 256; 2 per thread
#pragma unroll
    for (int kk = 0; kk < 2; kk++) {
        int lin = kk * 128 + tid;
        int gk = lin >> 5, c4 = lin & 31;
        float4 v;
        if (y == 0)       v = w1v4[gk * 32 + c4];
        else              v = w2v4[gk * 32 + c4];   // tile 0 rows < 128
        swv[lin] = v;
    }
    __syncthreads();

    for (int t = 0; t < NT; t++) {
        int cb = t & 1, nb = cb ^ 1;
        if (t + 1 < NT) {
            int k0n = (t + 1) * 8;
#pragma unroll
            for (int kk = 0; kk < 2; kk++) {
                int lin = kk * 128 + tid;
                int gk = k0n + (lin >> 5), c4 = lin & 31;
                float4 v;
                if (y == 0)           v = w1v4[gk * 32 + c4];
                else if (gk < HH)     v = w2v4[gk * 32 + c4];
                else                  v = w3v4[(gk - HH) * 32 + c4];
                swv[nb * 256 + lin] = v;
            }
        }
        int k0 = t * 8;
#pragma unroll
        for (int hl = 0; hl < 8; hl++) {
            float4 w4 = swv[cb * 256 + hl * 32 + cg];
            float4 va = *(const float4*)&s_cat[k0 + hl][rg * 8];
            float4 vb = *(const float4*)&s_cat[k0 + hl][rg * 8 + 4];
            float wv[4] = {w4.x, w4.y, w4.z, w4.w};
            float rv[8] = {va.x, va.y, va.z, va.w, vb.x, vb.y, vb.z, vb.w};
#pragma unroll
            for (int cc = 0; cc < 4; cc++)
#pragma unroll
                for (int rr = 0; rr < 8; rr++)
                    a0[cc * 8 + rr] = fmaf(wv[cc], rv[rr], a0[cc * 8 + rr]);
        }
        __syncthreads();
    }

    if (y == 0) {
        float4 bv = *(const float4*)&w1b[cg * 4];
        float bb[4] = {bv.x, bv.y, bv.z, bv.w};
#pragma unroll
        for (int cc = 0; cc < 4; cc++) {
            int col = cg * 4 + cc;
#pragma unroll
            for (int rr = 0; rr < 8; rr++) {
                int grow = row0 + rg * 8 + rr;
                int tt = grow >> 6;       // row = t*B + b
                int b  = grow & 63;
                g_x1T[(b * HH + col) * TT + tt] = a0[cc * 8 + rr] + bb[cc];
            }
        }
    } else {
#pragma unroll
        for (int cc = 0; cc < 4; cc++) {
            int col = cg * 4 + cc;
#pragma unroll
            for (int rr = 0; rr < 8; rr++) {
                int grow = row0 + rg * 8 + rr;
                g_q[grow * HH + col] = a0[cc * 8 + rr];
            }
        }
    }
}

// ---------------------------------------------------------------------------
// K3 v3: scores + m_a. One block per (i-tile of 16, b), 256 threads.
// Phase 1 x1T staged through smem in 16-h tiles -> inner loop pure LDS+MUFU.
// ---------------------------------------------------------------------------
__global__ __launch_bounds__(256) void k_scores(
    const float* __restrict__ in, const float* __restrict__ w0)
{
    int i0 = blockIdx.x * 16;
    int b  = blockIdx.y;
    __shared__ float qh[16][HH];      // 0.5 * q[i,b,:]
    __shared__ float w0s[HH];
    __shared__ float sx1[16][132];    // x1T tile [h-local][j], padded
    __shared__ float ssh[16][132];    // scores, padded
    __shared__ float w0sum_sh;

    int tid = threadIdx.x;
    int jlim = i0 + 16;               // causally relevant j range
    for (int idx = tid; idx < 16 * HH; idx += 256) {
        int il = idx >> 7, h = idx & 127;
        qh[il][h] = g_q[((i0 + il) * BB + b) * HH + h] * 0.5f;
    }
    if (tid < 128) w0s[tid] = w0[tid];
    __syncthreads();
    if (tid < 32) {
        float s = w0s[tid] + w0s[tid+32] + w0s[tid+64] + w0s[tid+96];
#pragma unroll
        for (int off = 16; off; off >>= 1) s += __shfl_xor_sync(0xFFFFFFFFu, s, off);
        if (tid == 0) w0sum_sh = s;
    }
    __syncthreads();
    float w0sum = w0sum_sh;

    // ---- phase 1: scores ----
    int j  = tid & 127;
    int ih = (tid >> 7) * 8;          // 8 i's per thread
    float acc[8];
#pragma unroll
    for (int k = 0; k < 8; k++) acc[k] = 0.0f;

    const float* xbase = g_x1T + b * (HH * TT);
    for (int ht = 0; ht < 8; ht++) {
        int h0 = ht * 16;
        // cooperative load of x1T tile: rows h0..h0+15, cols j<jlim
        for (int idx = tid; idx < 16 * HH; idx += 256) {
            int hl = idx >> 7, jj = idx & 127;
            if (jj < jlim) sx1[hl][jj] = xbase[(h0 + hl) * TT + jj];
        }
        __syncthreads();
        if (j < jlim) {
#pragma unroll
            for (int hl = 0; hl < 16; hl++) {
                float x1v = sx1[hl][j] * 0.5f;
                float wv = w0s[h0 + hl];
#pragma unroll
                for (int k = 0; k < 8; k++) {
                    float t = ftanh(x1v + qh[ih + k][h0 + hl]);
                    acc[k] = fmaf(wv, t, acc[k]);
                }
            }
        }
        __syncthreads();
    }
#pragma unroll
    for (int k = 0; k < 8; k++) {
        int ig = i0 + ih + k;
        ssh[ih + k][j] = (j <= ig) ? 0.5f * (acc[k] + w0sum) : 0.0f;
    }
    __syncthreads();

    // ---- phase 2: m_a ----
    int h   = tid & 127;
    int ih2 = (tid >> 7) * 8;
    float m[8];
#pragma unroll
    for (int k = 0; k < 8; k++) m[k] = 0.0f;

    const float* ip = in + b * HH + h;
    for (int jj = 0; jj < jlim; jj += 4) {
        float v0 = ip[(jj + 0) * (BB*HH)];
        float v1 = ip[(jj + 1) * (BB*HH)];
        float v2 = ip[(jj + 2) * (BB*HH)];
        float v3 = ip[(jj + 3) * (BB*HH)];
#pragma unroll
        for (int k = 0; k < 8; k++) {
            float4 s4 = *(const float4*)&ssh[ih2 + k][jj];
            m[k] = fmaf(s4.x, v0, fmaf(s4.y, v1, fmaf(s4.z, v2, fmaf(s4.w, v3, m[k]))));
        }
    }
#pragma unroll
    for (int k = 0; k < 8; k++)
        g_ma[((i0 + ih2 + k) * BB + b) * HH + h] = m[k];
}

// ---------------------------------------------------------------------------
// K4: predict MLP (frozen R8). grid (256, 4), 128 thr, 32 rows/block.
// ---------------------------------------------------------------------------
__global__ __launch_bounds__(128) void k_predict_mm(
    const float* __restrict__ in,
    const float* __restrict__ c0a, const float* __restrict__ c0ab,
    const float* __restrict__ c0b, const float* __restrict__ c0bb,
    const float* __restrict__ c1a, const float* __restrict__ c1ab,
    const float* __restrict__ c1b, const float* __restrict__ c1bb,
    const float* __restrict__ v0a, const float* __restrict__ v0ab,
    const float* __restrict__ v0b, const float* __restrict__ v0bb,
    const float* __restrict__ v1a, const float* __restrict__ v1ab,
    const float* __restrict__ v1b, const float* __restrict__ v1bb)
{
    __shared__ float s_in[HH][36];      // 18.4KB: inputs, then layer0 acts
    __shared__ float s_w[2][8][128];    // 8KB double-buffered weight tile

    int tid    = threadIdx.x;
    int row0   = blockIdx.x * 32;
    int pass   = blockIdx.y >> 1;
    int branch = blockIdx.y & 1;        // 0: a-side (m_a), 1: b-side (inputs)

    const float *k0, *k0bias, *k1, *k1bias;
    if (pass == 0) { k0 = branch ? c0b : c0a; k0bias = branch ? c0bb : c0ab;
                     k1 = branch ? c1b : c1a; k1bias = branch ? c1bb : c1ab; }
    else           { k0 = branch ? v0b : v0a; k0bias = branch ? v0bb : v0ab;
                     k1 = branch ? v1b : v1a; k1bias = branch ? v1bb : v1ab; }
    const float* src = branch ? in : g_ma;

    for (int idx = tid; idx < 32 * HH; idx += 128) {
        int h = idx & 127, r = idx >> 7;
        s_in[h][r] = src[(row0 + r) * HH + h];
    }

    int cg = tid & 31;
    int rg = tid >> 5;
    float a0[32];
#pragma unroll
    for (int x = 0; x < 32; x++) a0[x] = 0.0f;

    const float4* k0v = (const float4*)k0;
    float4* swv = (float4*)&s_w[0][0][0];
    swv[tid]       = k0v[(tid >> 5) * 32 + (tid & 31)];
    swv[128 + tid] = k0v[((128 + tid) >> 5) * 32 + (tid & 31)];
    __syncthreads();

    for (int t = 0; t < 16; t++) {
        int cb = t & 1, nb = cb ^ 1;
        if (t + 1 < 16) {
            int h0n = (t + 1) * 8;
#pragma unroll
            for (int kk = 0; kk < 2; kk++) {
                int lin = kk * 128 + tid;
                swv[nb * 256 + lin] = k0v[(h0n + (lin >> 5)) * 32 + (lin & 31)];
            }
        }
        int h0 = t * 8;
#pragma unroll
        for (int hl = 0; hl < 8; hl++) {
            float4 w4 = swv[cb * 256 + hl * 32 + cg];
            float4 va = *(const float4*)&s_in[h0 + hl][rg * 8];
            float4 vb = *(const float4*)&s_in[h0 + hl][rg * 8 + 4];
            float wv[4] = {w4.x, w4.y, w4.z, w4.w};
            float rv[8] = {va.x, va.y, va.z, va.w, vb.x, vb.y, vb.z, vb.w};
#pragma unroll
            for (int cc = 0; cc < 4; cc++)
#pragma unroll
                for (int rr = 0; rr < 8; rr++)
                    a0[cc * 8 + rr] = fmaf(wv[cc], rv[rr], a0[cc * 8 + rr]);
        }
        __syncthreads();
    }
    float4 b0v = *(const float4*)&k0bias[cg * 4];
    float b0[4] = {b0v.x, b0v.y, b0v.z, b0v.w};
#pragma unroll
    for (int cc = 0; cc < 4; cc++) {
        int col = cg * 4 + cc;
        float t0[8];
#pragma unroll
        for (int rr = 0; rr < 8; rr++) t0[rr] = leakyf_(a0[cc * 8 + rr] + b0[cc]);
        *(float4*)&s_in[col][rg * 8]     = make_float4(t0[0], t0[1], t0[2], t0[3]);
        *(float4*)&s_in[col][rg * 8 + 4] = make_float4(t0[4], t0[5], t0[6], t0[7]);
    }
    __syncthreads();

    int cg2 = tid & 15;
    int rg2 = tid >> 4;
    float a1[16];
#pragma unroll
    for (int x = 0; x < 16; x++) a1[x] = 0.0f;

    const float4* k1v = (const float4*)k1;
    swv[(tid >> 4) * 16 + (tid & 15)] = k1v[(tid >> 4) * 16 + (tid & 15)];
    __syncthreads();

    for (int t = 0; t < 16; t++) {
        int cb = t & 1, nb = cb ^ 1;
        if (t + 1 < 16) {
            int h0n = (t + 1) * 8;
            int hh = tid >> 4, c4 = tid & 15;
            swv[nb * 128 + hh * 16 + c4] = k1v[(h0n + hh) * 16 + c4];
        }
        int h0 = t * 8;
#pragma unroll
        for (int hl = 0; hl < 8; hl++) {
            float4 w4 = swv[cb * 128 + hl * 16 + cg2];
            float4 v4 = *(const float4*)&s_in[h0 + hl][rg2 * 4];
            float wv[4] = {w4.x, w4.y, w4.z, w4.w};
            float rv[4] = {v4.x, v4.y, v4.z, v4.w};
#pragma unroll
            for (int cc = 0; cc < 4; cc++)
#pragma unroll
                for (int rr = 0; rr < 4; rr++)
                    a1[cc * 4 + rr] = fmaf(wv[cc], rv[rr], a1[cc * 4 + rr]);
        }
        __syncthreads();
    }
    float4 b1v = *(const float4*)&k1bias[cg2 * 4];
    float b1[4] = {b1v.x, b1v.y, b1v.z, b1v.w};

    int pb = pass * 2 + branch;
#pragma unroll
    for (int cc = 0; cc < 4; cc++) {
        int cidx = cg2 * 4 + cc;
        float4 v = make_float4(leakyf_(a1[cc * 4 + 0] + b1[cc]),
                               leakyf_(a1[cc * 4 + 1] + b1[cc]),
                               leakyf_(a1[cc * 4 + 2] + b1[cc]),
                               leakyf_(a1[cc * 4 + 3] + b1[cc]));
        *(float4*)&g_l1[(pb * EE1 + cidx) * TB + row0 + rg2 * 4] = v;
    }
}

// ---------------------------------------------------------------------------
// K5: combine — dot over E1, sigmoid, pv = sig*pc (frozen R8).
// ---------------------------------------------------------------------------
__global__ __launch_bounds__(256) void k_combine(float* __restrict__ out) {
    int row = blockIdx.x * 256 + threadIdx.x;    // 0..8191
    float s0 = 0.0f, s1 = 0.0f;
#pragma unroll 8
    for (int c = 0; c < EE1; c++) {
        float a0 = g_l1[(0 * EE1 + c) * TB + row];
        float b0 = g_l1[(1 * EE1 + c) * TB + row];
        float a1 = g_l1[(2 * EE1 + c) * TB + row];
        float b1 = g_l1[(3 * EE1 + c) * TB + row];
        s0 = fmaf(a0, b0, s0);
        s1 = fmaf(a1, b1, s1);
    }
    float pc = sigmoidf_(s0);
    out[row] = pc;
    out[TB + row] = sigmoidf_(s1) * pc;
}

// ---------------------------------------------------------------------------
extern "C" void kernel_launch(void* const* d_in, const int* in_sizes, int n_in,
                              void* d_out, int out_size)
{
    (void)in_sizes; (void)n_in; (void)out_size;
    const float* in_  = (const float*)d_in[0];
    const float* w1k  = (const float*)d_in[1];
    const float* w1b  = (const float*)d_in[2];
    const float* w2k  = (const float*)d_in[3];
    const float* w3k  = (const float*)d_in[4];
    const float* w0k  = (const float*)d_in[5];
    const float* pc0a = (const float*)d_in[6];
    const float* pc0ab= (const float*)d_in[7];
    const float* pc0b = (const float*)d_in[8];
    const float* pc0bb= (const float*)d_in[9];
    const float* pc1a = (const float*)d_in[10];
    const float* pc1ab= (const float*)d_in[11];
    const float* pc1b = (const float*)d_in[12];
    const float* pc1bb= (const float*)d_in[13];
    const float* pv0a = (const float*)d_in[14];
    const float* pv0ab= (const float*)d_in[15];
    const float* pv0b = (const float*)d_in[16];
    const float* pv0bb= (const float*)d_in[17];
    const float* pv1a = (const float*)d_in[18];
    const float* pv1ab= (const float*)d_in[19];
    const float* pv1b = (const float*)d_in[20];
    const float* pv1bb= (const float*)d_in[21];
    float* out = (float*)d_out;

    k_cumsum<<<BB*HH/128, 128>>>(in_);
    k_gemm1<<<dim3(TB/32, 2), 128>>>(in_, w1k, w1b, w2k, w3k);
    k_scores<<<dim3(TT/16, BB), 256>>>(in_, w0k);
    k_predict_mm<<<dim3(TB/32, 4), 128>>>(in_,
        pc0a, pc0ab, pc0b, pc0bb, pc1a, pc1ab, pc1b, pc1bb,
        pv0a, pv0ab, pv0b, pv0bb, pv1a, pv1ab, pv1b, pv1bb);
    k_combine<<<TB/256, 256>>>(out);
}

// round 11
// speedup vs baseline: 1.1796x; 1.1527x over previous
#include <cuda_runtime.h>

#define TT 128
#define BB 64
#define HH 128
#define EE0 128
#define EE1 64
#define TB (TT*BB)
#define BH (BB*HH)
#define LOG2E 1.4426950408889634f

// Scratch (device globals: no allocation allowed in kernel_launch)
__device__ float g_x1T[BB*HH*TT];   // x1 transposed [B,H,T]
__device__ float g_q[TT*BB*HH];     // x2, then q = x2 + cum(y)/(t+1)
__device__ float g_y[TT*BB*HH];     // in@w3, then in-chunk prefix sums
__device__ float g_ps[8*BH];        // per-chunk totals
__device__ float g_ma[TT*BB*HH];    // m_a           [T,B,H]
__device__ float g_l1[4*EE1*TB];    // layer1 outs [pass*2+branch][c][row]

__device__ __forceinline__ float fex2(float x){ float r; asm("ex2.approx.f32 %0, %1;" : "=f"(r) : "f"(x)); return r; }
__device__ __forceinline__ float frcp(float x){ float r; asm("rcp.approx.f32 %0, %1;" : "=f"(r) : "f"(x)); return r; }
__device__ __forceinline__ float ftanh(float x){ float r; asm("tanh.approx.f32 %0, %1;" : "=f"(r) : "f"(x)); return r; }
__device__ __forceinline__ float sigmoidf_(float x){ return frcp(1.0f + fex2(x * -LOG2E)); }
__device__ __forceinline__ float leakyf_(float x){ return x > 0.0f ? x : 0.3f * x; }

// ---------------------------------------------------------------------------
// K1: triple GEMM, uniform K=128. grid (256, 3), 128 thr, 32 rows/block.
//   y==0: x1 = in@w1 + b1 -> g_x1T (transposed)
//   y==1: x2 = in@w2      -> g_q   (q finished by qfixB)
//   y==2: y  = in@w3      -> g_y
// predict_mm loop shape: 4 cols x 8 rows/thread, double-buffered smem weights.
// ---------------------------------------------------------------------------
__global__ __launch_bounds__(128) void k_gemm3(
    const float* __restrict__ in,
    const float* __restrict__ w1, const float* __restrict__ w1b,
    const float* __restrict__ w2, const float* __restrict__ w3)
{
    __shared__ float s_in[HH][36];      // 18.4KB input tile transposed
    __shared__ float s_w[2][8][128];    // 8KB double-buffered weight tile

    int tid  = threadIdx.x;
    int row0 = blockIdx.x * 32;
    int y    = blockIdx.y;              // 0: x1, 1: x2, 2: y

    const float* wsel = (y == 0) ? w1 : (y == 1) ? w2 : w3;

    for (int idx = tid; idx < 32 * HH; idx += 128) {
        int h = idx & 127, r = idx >> 7;
        s_in[h][r] = in[(row0 + r) * HH + h];
    }

    int cg = tid & 31;               // cols cg*4 .. cg*4+3  (== lane)
    int rg = tid >> 5;               // rows rg*8 .. rg*8+7  (== warp)
    float a0[32];
#pragma unroll
    for (int x = 0; x < 32; x++) a0[x] = 0.0f;

    const float4* kv = (const float4*)wsel;
    float4* swv = (float4*)&s_w[0][0][0];  // [2][8][32] float4 view
    swv[tid]       = kv[(tid >> 5) * 32 + (tid & 31)];
    swv[128 + tid] = kv[((128 + tid) >> 5) * 32 + (tid & 31)];
    __syncthreads();

    for (int t = 0; t < 16; t++) {
        int cb = t & 1, nb = cb ^ 1;
        if (t + 1 < 16) {
            int h0n = (t + 1) * 8;
#pragma unroll
            for (int kk = 0; kk < 2; kk++) {
                int lin = kk * 128 + tid;
                swv[nb * 256 + lin] = kv[(h0n + (lin >> 5)) * 32 + (lin & 31)];
            }
        }
        int h0 = t * 8;
#pragma unroll
        for (int hl = 0; hl < 8; hl++) {
            float4 w4 = swv[cb * 256 + hl * 32 + cg];
            float4 va = *(const float4*)&s_in[h0 + hl][rg * 8];
            float4 vb = *(const float4*)&s_in[h0 + hl][rg * 8 + 4];
            float wv[4] = {w4.x, w4.y, w4.z, w4.w};
            float rv[8] = {va.x, va.y, va.z, va.w, vb.x, vb.y, vb.z, vb.w};
#pragma unroll
            for (int cc = 0; cc < 4; cc++)
#pragma unroll
                for (int rr = 0; rr < 8; rr++)
                    a0[cc * 8 + rr] = fmaf(wv[cc], rv[rr], a0[cc * 8 + rr]);
        }
        __syncthreads();
    }

    if (y == 0) {
        float4 bv = *(const float4*)&w1b[cg * 4];
        float bb[4] = {bv.x, bv.y, bv.z, bv.w};
#pragma unroll
        for (int cc = 0; cc < 4; cc++) {
            int col = cg * 4 + cc;
#pragma unroll
            for (int rr = 0; rr < 8; rr++) {
                int grow = row0 + rg * 8 + rr;
                int tt = grow >> 6;       // row = t*B + b
                int b  = grow & 63;
                g_x1T[(b * HH + col) * TT + tt] = a0[cc * 8 + rr] + bb[cc];
            }
        }
    } else {
        float* dst = (y == 1) ? g_q : g_y;
#pragma unroll
        for (int rr = 0; rr < 8; rr++) {
            int grow = row0 + rg * 8 + rr;
            float4 v = make_float4(a0[0 * 8 + rr], a0[1 * 8 + rr],
                                   a0[2 * 8 + rr], a0[3 * 8 + rr]);
            *(float4*)&dst[grow * HH + cg * 4] = v;   // coalesced STG.128
        }
    }
}

// ---------------------------------------------------------------------------
// K2a: parallel scan phase A — 16-t chunk local prefixes (in-place on g_y)
// and chunk totals to g_ps. 65536 threads.
// ---------------------------------------------------------------------------
__global__ __launch_bounds__(256) void k_qfixA() {
    int gid = blockIdx.x * 256 + threadIdx.x;   // 0..65535
    int c   = gid >> 13;                        // chunk 0..7
    int idx = gid & (BH - 1);                   // (b,h) 0..8191
    float acc = 0.0f;
#pragma unroll
    for (int k = 0; k < 16; k++) {
        int t = c * 16 + k;
        acc += g_y[t * BH + idx];
        g_y[t * BH + idx] = acc;                // local prefix incl. current
    }
    g_ps[c * BH + idx] = acc;                   // chunk total
}

// ---------------------------------------------------------------------------
// K2b: scan phase B — add chunk offsets, finish q = x2 + cum/(t+1). 1M thr.
// ---------------------------------------------------------------------------
__global__ __launch_bounds__(256) void k_qfixB() {
    int gid = blockIdx.x * 256 + threadIdx.x;   // 0..2^20-1
    int t   = gid >> 13;
    int idx = gid & (BH - 1);
    int c   = t >> 4;
    float off = 0.0f;
    for (int cc = 0; cc < c; cc++)
        off += g_ps[cc * BH + idx];
    float cum = off + g_y[gid];
    g_q[gid] += cum / (float)(t + 1);
}

// ---------------------------------------------------------------------------
// K3: scores + m_a (R10 version, heavy tiles launched first).
// ---------------------------------------------------------------------------
__global__ __launch_bounds__(256) void k_scores(
    const float* __restrict__ in, const float* __restrict__ w0)
{
    int i0 = (TT/16 - 1 - blockIdx.x) * 16;   // heavy-first
    int b  = blockIdx.y;
    __shared__ float qh[16][HH];      // 0.5 * q[i,b,:]
    __shared__ float w0s[HH];
    __shared__ float sx1[16][132];    // x1T tile [h-local][j], padded
    __shared__ float ssh[16][132];    // scores, padded
    __shared__ float w0sum_sh;

    int tid = threadIdx.x;
    int jlim = i0 + 16;               // causally relevant j range
    for (int idx = tid; idx < 16 * HH; idx += 256) {
        int il = idx >> 7, h = idx & 127;
        qh[il][h] = g_q[((i0 + il) * BB + b) * HH + h] * 0.5f;
    }
    if (tid < 128) w0s[tid] = w0[tid];
    __syncthreads();
    if (tid < 32) {
        float s = w0s[tid] + w0s[tid+32] + w0s[tid+64] + w0s[tid+96];
#pragma unroll
        for (int off = 16; off; off >>= 1) s += __shfl_xor_sync(0xFFFFFFFFu, s, off);
        if (tid == 0) w0sum_sh = s;
    }
    __syncthreads();
    float w0sum = w0sum_sh;

    // ---- phase 1: scores ----
    int j  = tid & 127;
    int ih = (tid >> 7) * 8;          // 8 i's per thread
    float acc[8];
#pragma unroll
    for (int k = 0; k < 8; k++) acc[k] = 0.0f;

    const float* xbase = g_x1T + b * (HH * TT);
    for (int ht = 0; ht < 8; ht++) {
        int h0 = ht * 16;
        for (int idx = tid; idx < 16 * HH; idx += 256) {
            int hl = idx >> 7, jj = idx & 127;
            if (jj < jlim) sx1[hl][jj] = xbase[(h0 + hl) * TT + jj];
        }
        __syncthreads();
        if (j < jlim) {
#pragma unroll
            for (int hl = 0; hl < 16; hl++) {
                float x1v = sx1[hl][j] * 0.5f;
                float wv = w0s[h0 + hl];
#pragma unroll
                for (int k = 0; k < 8; k++) {
                    float t = ftanh(x1v + qh[ih + k][h0 + hl]);
                    acc[k] = fmaf(wv, t, acc[k]);
                }
            }
        }
        __syncthreads();
    }
#pragma unroll
    for (int k = 0; k < 8; k++) {
        int ig = i0 + ih + k;
        ssh[ih + k][j] = (j <= ig) ? 0.5f * (acc[k] + w0sum) : 0.0f;
    }
    __syncthreads();

    // ---- phase 2: m_a ----
    int h   = tid & 127;
    int ih2 = (tid >> 7) * 8;
    float m[8];
#pragma unroll
    for (int k = 0; k < 8; k++) m[k] = 0.0f;

    const float* ip = in + b * HH + h;
    for (int jj = 0; jj < jlim; jj += 4) {
        float v0 = ip[(jj + 0) * (BB*HH)];
        float v1 = ip[(jj + 1) * (BB*HH)];
        float v2 = ip[(jj + 2) * (BB*HH)];
        float v3 = ip[(jj + 3) * (BB*HH)];
#pragma unroll
        for (int k = 0; k < 8; k++) {
            float4 s4 = *(const float4*)&ssh[ih2 + k][jj];
            m[k] = fmaf(s4.x, v0, fmaf(s4.y, v1, fmaf(s4.z, v2, fmaf(s4.w, v3, m[k]))));
        }
    }
#pragma unroll
    for (int k = 0; k < 8; k++)
        g_ma[((i0 + ih2 + k) * BB + b) * HH + h] = m[k];
}

// ---------------------------------------------------------------------------
// K4: predict MLP (frozen R8). grid (256, 4), 128 thr, 32 rows/block.
// ---------------------------------------------------------------------------
__global__ __launch_bounds__(128) void k_predict_mm(
    const float* __restrict__ in,
    const float* __restrict__ c0a, const float* __restrict__ c0ab,
    const float* __restrict__ c0b, const float* __restrict__ c0bb,
    const float* __restrict__ c1a, const float* __restrict__ c1ab,
    const float* __restrict__ c1b, const float* __restrict__ c1bb,
    const float* __restrict__ v0a, const float* __restrict__ v0ab,
    const float* __restrict__ v0b, const float* __restrict__ v0bb,
    const float* __restrict__ v1a, const float* __restrict__ v1ab,
    const float* __restrict__ v1b, const float* __restrict__ v1bb)
{
    __shared__ float s_in[HH][36];      // 18.4KB: inputs, then layer0 acts
    __shared__ float s_w[2][8][128];    // 8KB double-buffered weight tile

    int tid    = threadIdx.x;
    int row0   = blockIdx.x * 32;
    int pass   = blockIdx.y >> 1;
    int branch = blockIdx.y & 1;        // 0: a-side (m_a), 1: b-side (inputs)

    const float *k0, *k0bias, *k1, *k1bias;
    if (pass == 0) { k0 = branch ? c0b : c0a; k0bias = branch ? c0bb : c0ab;
                     k1 = branch ? c1b : c1a; k1bias = branch ? c1bb : c1ab; }
    else           { k0 = branch ? v0b : v0a; k0bias = branch ? v0bb : v0ab;
                     k1 = branch ? v1b : v1a; k1bias = branch ? v1bb : v1ab; }
    const float* src = branch ? in : g_ma;

    for (int idx = tid; idx < 32 * HH; idx += 128) {
        int h = idx & 127, r = idx >> 7;
        s_in[h][r] = src[(row0 + r) * HH + h];
    }

    int cg = tid & 31;
    int rg = tid >> 5;
    float a0[32];
#pragma unroll
    for (int x = 0; x < 32; x++) a0[x] = 0.0f;

    const float4* k0v = (const float4*)k0;
    float4* swv = (float4*)&s_w[0][0][0];
    swv[tid]       = k0v[(tid >> 5) * 32 + (tid & 31)];
    swv[128 + tid] = k0v[((128 + tid) >> 5) * 32 + (tid & 31)];
    __syncthreads();

    for (int t = 0; t < 16; t++) {
        int cb = t & 1, nb = cb ^ 1;
        if (t + 1 < 16) {
            int h0n = (t + 1) * 8;
#pragma unroll
            for (int kk = 0; kk < 2; kk++) {
                int lin = kk * 128 + tid;
                swv[nb * 256 + lin] = k0v[(h0n + (lin >> 5)) * 32 + (lin & 31)];
            }
        }
        int h0 = t * 8;
#pragma unroll
        for (int hl = 0; hl < 8; hl++) {
            float4 w4 = swv[cb * 256 + hl * 32 + cg];
            float4 va = *(const float4*)&s_in[h0 + hl][rg * 8];
            float4 vb = *(const float4*)&s_in[h0 + hl][rg * 8 + 4];
            float wv[4] = {w4.x, w4.y, w4.z, w4.w};
            float rv[8] = {va.x, va.y, va.z, va.w, vb.x, vb.y, vb.z, vb.w};
#pragma unroll
            for (int cc = 0; cc < 4; cc++)
#pragma unroll
                for (int rr = 0; rr < 8; rr++)
                    a0[cc * 8 + rr] = fmaf(wv[cc], rv[rr], a0[cc * 8 + rr]);
        }
        __syncthreads();
    }
    float4 b0v = *(const float4*)&k0bias[cg * 4];
    float b0[4] = {b0v.x, b0v.y, b0v.z, b0v.w};
#pragma unroll
    for (int cc = 0; cc < 4; cc++) {
        int col = cg * 4 + cc;
        float t0[8];
#pragma unroll
        for (int rr = 0; rr < 8; rr++) t0[rr] = leakyf_(a0[cc * 8 + rr] + b0[cc]);
        *(float4*)&s_in[col][rg * 8]     = make_float4(t0[0], t0[1], t0[2], t0[3]);
        *(float4*)&s_in[col][rg * 8 + 4] = make_float4(t0[4], t0[5], t0[6], t0[7]);
    }
    __syncthreads();

    int cg2 = tid & 15;
    int rg2 = tid >> 4;
    float a1[16];
#pragma unroll
    for (int x = 0; x < 16; x++) a1[x] = 0.0f;

    const float4* k1v = (const float4*)k1;
    swv[(tid >> 4) * 16 + (tid & 15)] = k1v[(tid >> 4) * 16 + (tid & 15)];
    __syncthreads();

    for (int t = 0; t < 16; t++) {
        int cb = t & 1, nb = cb ^ 1;
        if (t + 1 < 16) {
            int h0n = (t + 1) * 8;
            int hh = tid >> 4, c4 = tid & 15;
            swv[nb * 128 + hh * 16 + c4] = k1v[(h0n + hh) * 16 + c4];
        }
        int h0 = t * 8;
#pragma unroll
        for (int hl = 0; hl < 8; hl++) {
            float4 w4 = swv[cb * 128 + hl * 16 + cg2];
            float4 v4 = *(const float4*)&s_in[h0 + hl][rg2 * 4];
            float wv[4] = {w4.x, w4.y, w4.z, w4.w};
            float rv[4] = {v4.x, v4.y, v4.z, v4.w};
#pragma unroll
            for (int cc = 0; cc < 4; cc++)
#pragma unroll
                for (int rr = 0; rr < 4; rr++)
                    a1[cc * 4 + rr] = fmaf(wv[cc], rv[rr], a1[cc * 4 + rr]);
        }
        __syncthreads();
    }
    float4 b1v = *(const float4*)&k1bias[cg2 * 4];
    float b1[4] = {b1v.x, b1v.y, b1v.z, b1v.w};

    int pb = pass * 2 + branch;
#pragma unroll
    for (int cc = 0; cc < 4; cc++) {
        int cidx = cg2 * 4 + cc;
        float4 v = make_float4(leakyf_(a1[cc * 4 + 0] + b1[cc]),
                               leakyf_(a1[cc * 4 + 1] + b1[cc]),
                               leakyf_(a1[cc * 4 + 2] + b1[cc]),
                               leakyf_(a1[cc * 4 + 3] + b1[cc]));
        *(float4*)&g_l1[(pb * EE1 + cidx) * TB + row0 + rg2 * 4] = v;
    }
}

// ---------------------------------------------------------------------------
// K5: combine — dot over E1, sigmoid, pv = sig*pc (frozen R8).
// ---------------------------------------------------------------------------
__global__ __launch_bounds__(256) void k_combine(float* __restrict__ out) {
    int row = blockIdx.x * 256 + threadIdx.x;    // 0..8191
    float s0 = 0.0f, s1 = 0.0f;
#pragma unroll 8
    for (int c = 0; c < EE1; c++) {
        float a0 = g_l1[(0 * EE1 + c) * TB + row];
        float b0 = g_l1[(1 * EE1 + c) * TB + row];
        float a1 = g_l1[(2 * EE1 + c) * TB + row];
        float b1 = g_l1[(3 * EE1 + c) * TB + row];
        s0 = fmaf(a0, b0, s0);
        s1 = fmaf(a1, b1, s1);
    }
    float pc = sigmoidf_(s0);
    out[row] = pc;
    out[TB + row] = sigmoidf_(s1) * pc;
}

// ---------------------------------------------------------------------------
extern "C" void kernel_launch(void* const* d_in, const int* in_sizes, int n_in,
                              void* d_out, int out_size)
{
    (void)in_sizes; (void)n_in; (void)out_size;
    const float* in_  = (const float*)d_in[0];
    const float* w1k  = (const float*)d_in[1];
    const float* w1b  = (const float*)d_in[2];
    const float* w2k  = (const float*)d_in[3];
    const float* w3k  = (const float*)d_in[4];
    const float* w0k  = (const float*)d_in[5];
    const float* pc0a = (const float*)d_in[6];
    const float* pc0ab= (const float*)d_in[7];
    const float* pc0b = (const float*)d_in[8];
    const float* pc0bb= (const float*)d_in[9];
    const float* pc1a = (const float*)d_in[10];
    const float* pc1ab= (const float*)d_in[11];
    const float* pc1b = (const float*)d_in[12];
    const float* pc1bb= (const float*)d_in[13];
    const float* pv0a = (const float*)d_in[14];
    const float* pv0ab= (const float*)d_in[15];
    const float* pv0b = (const float*)d_in[16];
    const float* pv0bb= (const float*)d_in[17];
    const float* pv1a = (const float*)d_in[18];
    const float* pv1ab= (const float*)d_in[19];
    const float* pv1b = (const float*)d_in[20];
    const float* pv1bb= (const float*)d_in[21];
    float* out = (float*)d_out;

    k_gemm3<<<dim3(TB/32, 3), 128>>>(in_, w1k, w1b, w2k, w3k);
    k_qfixA<<<8*BH/256, 256>>>();
    k_qfixB<<<TT*BH/256, 256>>>();
    k_scores<<<dim3(TT/16, BB), 256>>>(in_, w0k);
    k_predict_mm<<<dim3(TB/32, 4), 128>>>(in_,
        pc0a, pc0ab, pc0b, pc0bb, pc1a, pc1ab, pc1b, pc1bb,
        pv0a, pv0ab, pv0b, pv0bb, pv1a, pv1ab, pv1b, pv1bb);
    k_combine<<<TB/256, 256>>>(out);
}

// round 12
// speedup vs baseline: 1.1841x; 1.0038x over previous
#include <cuda_runtime.h>

#define TT 128
#define BB 64
#define HH 128
#define EE0 128
#define EE1 64
#define TB (TT*BB)
#define BH (BB*HH)
#define LOG2E 1.4426950408889634f

// Scratch (device globals: no allocation allowed in kernel_launch)
__device__ float g_x1T[BB*HH*TT];   // x1 transposed [B,H,T]
__device__ float g_q[TT*BB*HH];     // x2, then q = x2 + cum(y)/(t+1)
__device__ float g_y[TT*BB*HH];     // in@w3, then in-chunk prefix sums
__device__ float g_ps[8*BH];        // per-chunk totals
__device__ float g_ma[TT*BB*HH];    // m_a           [T,B,H]
__device__ float g_l1[4*EE1*TB];    // layer1 outs [pass*2+branch][c][row]

__device__ __forceinline__ float fex2(float x){ float r; asm("ex2.approx.f32 %0, %1;" : "=f"(r) : "f"(x)); return r; }
__device__ __forceinline__ float frcp(float x){ float r; asm("rcp.approx.f32 %0, %1;" : "=f"(r) : "f"(x)); return r; }
__device__ __forceinline__ float ftanh(float x){ float r; asm("tanh.approx.f32 %0, %1;" : "=f"(r) : "f"(x)); return r; }
__device__ __forceinline__ float sigmoidf_(float x){ return frcp(1.0f + fex2(x * -LOG2E)); }
__device__ __forceinline__ float leakyf_(float x){ return x > 0.0f ? x : 0.3f * x; }

// ---------------------------------------------------------------------------
// K1: triple GEMM, uniform K=128. grid (256, 3), 128 thr, 32 rows/block.
// (frozen R11)
// ---------------------------------------------------------------------------
__global__ __launch_bounds__(128) void k_gemm3(
    const float* __restrict__ in,
    const float* __restrict__ w1, const float* __restrict__ w1b,
    const float* __restrict__ w2, const float* __restrict__ w3)
{
    __shared__ float s_in[HH][36];      // 18.4KB input tile transposed
    __shared__ float s_w[2][8][128];    // 8KB double-buffered weight tile

    int tid  = threadIdx.x;
    int row0 = blockIdx.x * 32;
    int y    = blockIdx.y;              // 0: x1, 1: x2, 2: y

    const float* wsel = (y == 0) ? w1 : (y == 1) ? w2 : w3;

    for (int idx = tid; idx < 32 * HH; idx += 128) {
        int h = idx & 127, r = idx >> 7;
        s_in[h][r] = in[(row0 + r) * HH + h];
    }

    int cg = tid & 31;               // cols cg*4 .. cg*4+3  (== lane)
    int rg = tid >> 5;               // rows rg*8 .. rg*8+7  (== warp)
    float a0[32];
#pragma unroll
    for (int x = 0; x < 32; x++) a0[x] = 0.0f;

    const float4* kv = (const float4*)wsel;
    float4* swv = (float4*)&s_w[0][0][0];  // [2][8][32] float4 view
    swv[tid]       = kv[(tid >> 5) * 32 + (tid & 31)];
    swv[128 + tid] = kv[((128 + tid) >> 5) * 32 + (tid & 31)];
    __syncthreads();

    for (int t = 0; t < 16; t++) {
        int cb = t & 1, nb = cb ^ 1;
        if (t + 1 < 16) {
            int h0n = (t + 1) * 8;
#pragma unroll
            for (int kk = 0; kk < 2; kk++) {
                int lin = kk * 128 + tid;
                swv[nb * 256 + lin] = kv[(h0n + (lin >> 5)) * 32 + (lin & 31)];
            }
        }
        int h0 = t * 8;
#pragma unroll
        for (int hl = 0; hl < 8; hl++) {
            float4 w4 = swv[cb * 256 + hl * 32 + cg];
            float4 va = *(const float4*)&s_in[h0 + hl][rg * 8];
            float4 vb = *(const float4*)&s_in[h0 + hl][rg * 8 + 4];
            float wv[4] = {w4.x, w4.y, w4.z, w4.w};
            float rv[8] = {va.x, va.y, va.z, va.w, vb.x, vb.y, vb.z, vb.w};
#pragma unroll
            for (int cc = 0; cc < 4; cc++)
#pragma unroll
                for (int rr = 0; rr < 8; rr++)
                    a0[cc * 8 + rr] = fmaf(wv[cc], rv[rr], a0[cc * 8 + rr]);
        }
        __syncthreads();
    }

    if (y == 0) {
        float4 bv = *(const float4*)&w1b[cg * 4];
        float bb[4] = {bv.x, bv.y, bv.z, bv.w};
#pragma unroll
        for (int cc = 0; cc < 4; cc++) {
            int col = cg * 4 + cc;
#pragma unroll
            for (int rr = 0; rr < 8; rr++) {
                int grow = row0 + rg * 8 + rr;
                int tt = grow >> 6;       // row = t*B + b
                int b  = grow & 63;
                g_x1T[(b * HH + col) * TT + tt] = a0[cc * 8 + rr] + bb[cc];
            }
        }
    } else {
        float* dst = (y == 1) ? g_q : g_y;
#pragma unroll
        for (int rr = 0; rr < 8; rr++) {
            int grow = row0 + rg * 8 + rr;
            float4 v = make_float4(a0[0 * 8 + rr], a0[1 * 8 + rr],
                                   a0[2 * 8 + rr], a0[3 * 8 + rr]);
            *(float4*)&dst[grow * HH + cg * 4] = v;   // coalesced STG.128
        }
    }
}

// ---------------------------------------------------------------------------
// K2a: scan phase A (frozen R11).
// ---------------------------------------------------------------------------
__global__ __launch_bounds__(256) void k_qfixA() {
    int gid = blockIdx.x * 256 + threadIdx.x;   // 0..65535
    int c   = gid >> 13;                        // chunk 0..7
    int idx = gid & (BH - 1);                   // (b,h) 0..8191
    float acc = 0.0f;
#pragma unroll
    for (int k = 0; k < 16; k++) {
        int t = c * 16 + k;
        acc += g_y[t * BH + idx];
        g_y[t * BH + idx] = acc;                // local prefix incl. current
    }
    g_ps[c * BH + idx] = acc;                   // chunk total
}

// ---------------------------------------------------------------------------
// K2b: scan phase B (frozen R11).
// ---------------------------------------------------------------------------
__global__ __launch_bounds__(256) void k_qfixB() {
    int gid = blockIdx.x * 256 + threadIdx.x;   // 0..2^20-1
    int t   = gid >> 13;
    int idx = gid & (BH - 1);
    int c   = t >> 4;
    float off = 0.0f;
    for (int cc = 0; cc < c; cc++)
        off += g_ps[cc * BH + idx];
    float cum = off + g_y[gid];
    g_q[gid] += cum / (float)(t + 1);
}

// ---------------------------------------------------------------------------
// K3 v4: scores + m_a. 512 threads, 4 i's/thread, grid (8, 64), heavy-first.
//  - qh TRANSPOSED [h][i-local] -> per-hl q loads are one broadcast LDS.128
//  - x1 and q pre-scaled by 0.5 at load time
//  - sx1 double-buffered: 1 sync per 16-h tile, LDG overlapped with compute
//  - __launch_bounds__(512,3) -> <=42 regs, 3 blocks/SM (75% occ target)
// ---------------------------------------------------------------------------
__global__ __launch_bounds__(512, 3) void k_scores(
    const float* __restrict__ in, const float* __restrict__ w0)
{
    int i0 = (TT/16 - 1 - blockIdx.x) * 16;   // heavy-first
    int b  = blockIdx.y;
    __shared__ float qhT[HH][20];     // 0.5*q, transposed: [h][i-local], padded
    __shared__ float w0s[HH];
    __shared__ float sx1[2][16][132]; // 0.5*x1T tiles, double-buffered
    __shared__ float ssh[16][132];    // scores, padded
    __shared__ float w0sum_sh;

    int tid = threadIdx.x;
    int jlim = i0 + 16;               // causally relevant j range

    // qhT load: coalesced over h, scatter to smem (padded rows)
    for (int idx = tid; idx < 16 * HH; idx += 512) {
        int il = idx >> 7, h = idx & 127;
        qhT[h][il] = g_q[((i0 + il) * BB + b) * HH + h] * 0.5f;
    }
    if (tid < 128) w0s[tid] = w0[tid];
    __syncthreads();
    if (tid < 32) {
        float s = w0s[tid] + w0s[tid+32] + w0s[tid+64] + w0s[tid+96];
#pragma unroll
        for (int off = 16; off; off >>= 1) s += __shfl_xor_sync(0xFFFFFFFFu, s, off);
        if (tid == 0) w0sum_sh = s;
    }

    // ---- phase 1: scores ----
    int j  = tid & 127;
    int ih = (tid >> 7) * 4;          // 4 i's per thread
    float acc[4] = {0.0f, 0.0f, 0.0f, 0.0f};

    const float* xbase = g_x1T + b * (HH * TT);
    // preload tile 0 (pre-scaled by 0.5)
    for (int idx = tid; idx < 16 * HH; idx += 512) {
        int hl = idx >> 7, jj = idx & 127;
        if (jj < jlim) sx1[0][hl][jj] = xbase[hl * TT + jj] * 0.5f;
    }
    __syncthreads();
    float w0sum = w0sum_sh;

    for (int ht = 0; ht < 8; ht++) {
        int cb = ht & 1, nb = cb ^ 1;
        if (ht + 1 < 8) {
            int h0n = (ht + 1) * 16;
            for (int idx = tid; idx < 16 * HH; idx += 512) {
                int hl = idx >> 7, jj = idx & 127;
                if (jj < jlim) sx1[nb][hl][jj] = xbase[(h0n + hl) * TT + jj] * 0.5f;
            }
        }
        int h0 = ht * 16;
        if (j < jlim) {
#pragma unroll
            for (int hl = 0; hl < 16; hl++) {
                float x1v = sx1[cb][hl][j];
                float wv  = w0s[h0 + hl];
                float4 q4 = *(const float4*)&qhT[h0 + hl][ih];   // broadcast
                acc[0] = fmaf(wv, ftanh(x1v + q4.x), acc[0]);
                acc[1] = fmaf(wv, ftanh(x1v + q4.y), acc[1]);
                acc[2] = fmaf(wv, ftanh(x1v + q4.z), acc[2]);
                acc[3] = fmaf(wv, ftanh(x1v + q4.w), acc[3]);
            }
        }
        __syncthreads();
    }
#pragma unroll
    for (int k = 0; k < 4; k++) {
        int ig = i0 + ih + k;
        ssh[ih + k][j] = (j <= ig) ? 0.5f * (acc[k] + w0sum) : 0.0f;
    }
    __syncthreads();

    // ---- phase 2: m_a ----
    int h   = tid & 127;
    int ih2 = (tid >> 7) * 4;
    float m[4] = {0.0f, 0.0f, 0.0f, 0.0f};

    const float* ip = in + b * HH + h;
    for (int jj = 0; jj < jlim; jj += 4) {
        float v0 = ip[(jj + 0) * BH];
        float v1 = ip[(jj + 1) * BH];
        float v2 = ip[(jj + 2) * BH];
        float v3 = ip[(jj + 3) * BH];
#pragma unroll
        for (int k = 0; k < 4; k++) {
            float4 s4 = *(const float4*)&ssh[ih2 + k][jj];
            m[k] = fmaf(s4.x, v0, fmaf(s4.y, v1, fmaf(s4.z, v2, fmaf(s4.w, v3, m[k]))));
        }
    }
#pragma unroll
    for (int k = 0; k < 4; k++)
        g_ma[((i0 + ih2 + k) * BB + b) * HH + h] = m[k];
}

// ---------------------------------------------------------------------------
// K4: predict MLP (frozen R8). grid (256, 4), 128 thr, 32 rows/block.
// ---------------------------------------------------------------------------
__global__ __launch_bounds__(128) void k_predict_mm(
    const float* __restrict__ in,
    const float* __restrict__ c0a, const float* __restrict__ c0ab,
    const float* __restrict__ c0b, const float* __restrict__ c0bb,
    const float* __restrict__ c1a, const float* __restrict__ c1ab,
    const float* __restrict__ c1b, const float* __restrict__ c1bb,
    const float* __restrict__ v0a, const float* __restrict__ v0ab,
    const float* __restrict__ v0b, const float* __restrict__ v0bb,
    const float* __restrict__ v1a, const float* __restrict__ v1ab,
    const float* __restrict__ v1b, const float* __restrict__ v1bb)
{
    __shared__ float s_in[HH][36];      // 18.4KB: inputs, then layer0 acts
    __shared__ float s_w[2][8][128];    // 8KB double-buffered weight tile

    int tid    = threadIdx.x;
    int row0   = blockIdx.x * 32;
    int pass   = blockIdx.y >> 1;
    int branch = blockIdx.y & 1;        // 0: a-side (m_a), 1: b-side (inputs)

    const float *k0, *k0bias, *k1, *k1bias;
    if (pass == 0) { k0 = branch ? c0b : c0a; k0bias = branch ? c0bb : c0ab;
                     k1 = branch ? c1b : c1a; k1bias = branch ? c1bb : c1ab; }
    else           { k0 = branch ? v0b : v0a; k0bias = branch ? v0bb : v0ab;
                     k1 = branch ? v1b : v1a; k1bias = branch ? v1bb : v1ab; }
    const float* src = branch ? in : g_ma;

    for (int idx = tid; idx < 32 * HH; idx += 128) {
        int h = idx & 127, r = idx >> 7;
        s_in[h][r] = src[(row0 + r) * HH + h];
    }

    int cg = tid & 31;
    int rg = tid >> 5;
    float a0[32];
#pragma unroll
    for (int x = 0; x < 32; x++) a0[x] = 0.0f;

    const float4* k0v = (const float4*)k0;
    float4* swv = (float4*)&s_w[0][0][0];
    swv[tid]       = k0v[(tid >> 5) * 32 + (tid & 31)];
    swv[128 + tid] = k0v[((128 + tid) >> 5) * 32 + (tid & 31)];
    __syncthreads();

    for (int t = 0; t < 16; t++) {
        int cb = t & 1, nb = cb ^ 1;
        if (t + 1 < 16) {
            int h0n = (t + 1) * 8;
#pragma unroll
            for (int kk = 0; kk < 2; kk++) {
                int lin = kk * 128 + tid;
                swv[nb * 256 + lin] = k0v[(h0n + (lin >> 5)) * 32 + (lin & 31)];
            }
        }
        int h0 = t * 8;
#pragma unroll
        for (int hl = 0; hl < 8; hl++) {
            float4 w4 = swv[cb * 256 + hl * 32 + cg];
            float4 va = *(const float4*)&s_in[h0 + hl][rg * 8];
            float4 vb = *(const float4*)&s_in[h0 + hl][rg * 8 + 4];
            float wv[4] = {w4.x, w4.y, w4.z, w4.w};
            float rv[8] = {va.x, va.y, va.z, va.w, vb.x, vb.y, vb.z, vb.w};
#pragma unroll
            for (int cc = 0; cc < 4; cc++)
#pragma unroll
                for (int rr = 0; rr < 8; rr++)
                    a0[cc * 8 + rr] = fmaf(wv[cc], rv[rr], a0[cc * 8 + rr]);
        }
        __syncthreads();
    }
    float4 b0v = *(const float4*)&k0bias[cg * 4];
    float b0[4] = {b0v.x, b0v.y, b0v.z, b0v.w};
#pragma unroll
    for (int cc = 0; cc < 4; cc++) {
        int col = cg * 4 + cc;
        float t0[8];
#pragma unroll
        for (int rr = 0; rr < 8; rr++) t0[rr] = leakyf_(a0[cc * 8 + rr] + b0[cc]);
        *(float4*)&s_in[col][rg * 8]     = make_float4(t0[0], t0[1], t0[2], t0[3]);
        *(float4*)&s_in[col][rg * 8 + 4] = make_float4(t0[4], t0[5], t0[6], t0[7]);
    }
    __syncthreads();

    int cg2 = tid & 15;
    int rg2 = tid >> 4;
    float a1[16];
#pragma unroll
    for (int x = 0; x < 16; x++) a1[x] = 0.0f;

    const float4* k1v = (const float4*)k1;
    swv[(tid >> 4) * 16 + (tid & 15)] = k1v[(tid >> 4) * 16 + (tid & 15)];
    __syncthreads();

    for (int t = 0; t < 16; t++) {
        int cb = t & 1, nb = cb ^ 1;
        if (t + 1 < 16) {
            int h0n = (t + 1) * 8;
            int hh = tid >> 4, c4 = tid & 15;
            swv[nb * 128 + hh * 16 + c4] = k1v[(h0n + hh) * 16 + c4];
        }
        int h0 = t * 8;
#pragma unroll
        for (int hl = 0; hl < 8; hl++) {
            float4 w4 = swv[cb * 128 + hl * 16 + cg2];
            float4 v4 = *(const float4*)&s_in[h0 + hl][rg2 * 4];
            float wv[4] = {w4.x, w4.y, w4.z, w4.w};
            float rv[4] = {v4.x, v4.y, v4.z, v4.w};
#pragma unroll
            for (int cc = 0; cc < 4; cc++)
#pragma unroll
                for (int rr = 0; rr < 4; rr++)
                    a1[cc * 4 + rr] = fmaf(wv[cc], rv[rr], a1[cc * 4 + rr]);
        }
        __syncthreads();
    }
    float4 b1v = *(const float4*)&k1bias[cg2 * 4];
    float b1[4] = {b1v.x, b1v.y, b1v.z, b1v.w};

    int pb = pass * 2 + branch;
#pragma unroll
    for (int cc = 0; cc < 4; cc++) {
        int cidx = cg2 * 4 + cc;
        float4 v = make_float4(leakyf_(a1[cc * 4 + 0] + b1[cc]),
                               leakyf_(a1[cc * 4 + 1] + b1[cc]),
                               leakyf_(a1[cc * 4 + 2] + b1[cc]),
                               leakyf_(a1[cc * 4 + 3] + b1[cc]));
        *(float4*)&g_l1[(pb * EE1 + cidx) * TB + row0 + rg2 * 4] = v;
    }
}

// ---------------------------------------------------------------------------
// K5: combine — dot over E1, sigmoid, pv = sig*pc (frozen R8).
// ---------------------------------------------------------------------------
__global__ __launch_bounds__(256) void k_combine(float* __restrict__ out) {
    int row = blockIdx.x * 256 + threadIdx.x;    // 0..8191
    float s0 = 0.0f, s1 = 0.0f;
#pragma unroll 8
    for (int c = 0; c < EE1; c++) {
        float a0 = g_l1[(0 * EE1 + c) * TB + row];
        float b0 = g_l1[(1 * EE1 + c) * TB + row];
        float a1 = g_l1[(2 * EE1 + c) * TB + row];
        float b1 = g_l1[(3 * EE1 + c) * TB + row];
        s0 = fmaf(a0, b0, s0);
        s1 = fmaf(a1, b1, s1);
    }
    float pc = sigmoidf_(s0);
    out[row] = pc;
    out[TB + row] = sigmoidf_(s1) * pc;
}

// ---------------------------------------------------------------------------
extern "C" void kernel_launch(void* const* d_in, const int* in_sizes, int n_in,
                              void* d_out, int out_size)
{
    (void)in_sizes; (void)n_in; (void)out_size;
    const float* in_  = (const float*)d_in[0];
    const float* w1k  = (const float*)d_in[1];
    const float* w1b  = (const float*)d_in[2];
    const float* w2k  = (const float*)d_in[3];
    const float* w3k  = (const float*)d_in[4];
    const float* w0k  = (const float*)d_in[5];
    const float* pc0a = (const float*)d_in[6];
    const float* pc0ab= (const float*)d_in[7];
    const float* pc0b = (const float*)d_in[8];
    const float* pc0bb= (const float*)d_in[9];
    const float* pc1a = (const float*)d_in[10];
    const float* pc1ab= (const float*)d_in[11];
    const float* pc1b = (const float*)d_in[12];
    const float* pc1bb= (const float*)d_in[13];
    const float* pv0a = (const float*)d_in[14];
    const float* pv0ab= (const float*)d_in[15];
    const float* pv0b = (const float*)d_in[16];
    const float* pv0bb= (const float*)d_in[17];
    const float* pv1a = (const float*)d_in[18];
    const float* pv1ab= (const float*)d_in[19];
    const float* pv1b = (const float*)d_in[20];
    const float* pv1bb= (const float*)d_in[21];
    float* out = (float*)d_out;

    k_gemm3<<<dim3(TB/32, 3), 128>>>(in_, w1k, w1b, w2k, w3k);
    k_qfixA<<<8*BH/256, 256>>>();
    k_qfixB<<<TT*BH/256, 256>>>();
    k_scores<<<dim3(TT/16, BB), 512>>>(in_, w0k);
    k_predict_mm<<<dim3(TB/32, 4), 128>>>(in_,
        pc0a, pc0ab, pc0b, pc0bb, pc1a, pc1ab, pc1b, pc1bb,
        pv0a, pv0ab, pv0b, pv0bb, pv1a, pv1ab, pv1b, pv1bb);
    k_combine<<<TB/256, 256>>>(out);
}